// round 1
// baseline (speedup 1.0000x reference)
#include <cuda_runtime.h>
#include <math_constants.h>

// Problem constants (fixed shapes)
#define BG   64      // graphs
#define LG   1024    // nodes per graph
#define KNN  16      // neighbors
#define FIN  128     // in features
#define FOUT 128     // out features
#define SDIM 4       // space dims
#define FLR  64      // propagate dims
#define NTOT (BG*LG) // 65536

// Scratch (static device arrays — no allocation)
__device__ float g_s[NTOT * SDIM];          // 1 MB
__device__ float g_h[NTOT * FLR];           // 16 MB
__device__ int   g_idx[NTOT * KNN];         // 4 MB
__device__ float g_w[NTOT * KNN];           // 4 MB
__device__ float g_agg[NTOT * 2 * FLR];     // 32 MB  (mean ‖ max)

// ---------------------------------------------------------------------------
// Kernel 1: s = x@W_s + b_s ; h = x@W_h + b_h   (fused, 16 nodes per block)
// ---------------------------------------------------------------------------
__global__ __launch_bounds__(256) void k1_embed(
    const float* __restrict__ x,
    const float* __restrict__ Ws, const float* __restrict__ bs,
    const float* __restrict__ Wh, const float* __restrict__ bh)
{
    __shared__ float xs[16][FIN];
    const int n0 = blockIdx.x * 16;

    // stage 16 x-rows (2048 floats = 512 float4) into shared
    const float4* xg  = (const float4*)(x + (size_t)n0 * FIN);
    float4*       xs4 = (float4*)&xs[0][0];
    for (int i = threadIdx.x; i < 512; i += 256) xs4[i] = xg[i];
    __syncthreads();

    // 16 nodes * 68 outputs = 1088 elements
    for (int e = threadIdx.x; e < 16 * (SDIM + FLR); e += 256) {
        const int nl = e / (SDIM + FLR);
        const int j  = e % (SDIM + FLR);
        const float* xr = xs[nl];
        if (j < SDIM) {
            float acc = bs[j];
            #pragma unroll 8
            for (int k = 0; k < FIN; ++k) acc += xr[k] * Ws[k * SDIM + j];
            g_s[(size_t)(n0 + nl) * SDIM + j] = acc;
        } else {
            const int jh = j - SDIM;
            float acc = bh[jh];
            #pragma unroll 8
            for (int k = 0; k < FIN; ++k) acc += xr[k] * Wh[k * FLR + jh];
            g_h[(size_t)(n0 + nl) * FLR + jh] = acc;
        }
    }
}

// ---------------------------------------------------------------------------
// Kernel 2: per-graph kNN (top-16 smallest d2) + edge weights exp(-10 d2)
// grid = (LG/256, BG), block = 256. Whole graph's s (+sq) in shared.
// ---------------------------------------------------------------------------
__global__ __launch_bounds__(256) void k2_knn()
{
    __shared__ float4 ss[LG];
    __shared__ float  sqs[LG];

    const int g  = blockIdx.y;
    const int q0 = blockIdx.x * 256;

    const float4* sg4 = (const float4*)(g_s + (size_t)g * LG * SDIM);
    for (int i = threadIdx.x; i < LG; i += 256) {
        float4 v = sg4[i];
        ss[i]  = v;
        sqs[i] = ((v.x * v.x + v.y * v.y) + v.z * v.z) + v.w * v.w;
    }
    __syncthreads();

    const int q = q0 + threadIdx.x;
    const float4 si  = ss[q];
    const float  sqi = sqs[q];

    float bd[KNN];
    int   bi[KNN];
    #pragma unroll
    for (int p = 0; p < KNN; ++p) { bd[p] = CUDART_INF_F; bi[p] = -1; }

    for (int j = 0; j < LG; ++j) {
        const float4 sj = ss[j];
        const float dot = ((si.x * sj.x + si.y * sj.y) + si.z * sj.z) + si.w * sj.w;
        float d = sqi + sqs[j] - 2.0f * dot;
        d = fmaxf(d, 0.0f);
        if (d < bd[KNN - 1]) {
            float cd = d; int ci = j;
            #pragma unroll
            for (int p = 0; p < KNN; ++p) {
                if (cd < bd[p]) {   // strict < keeps stable (lowest-index) ordering
                    float td = bd[p]; int ti = bi[p];
                    bd[p] = cd; bi[p] = ci;
                    cd = td;   ci = ti;
                }
            }
        }
    }

    const size_t base = (size_t)(g * LG + q) * KNN;
    #pragma unroll
    for (int p = 0; p < KNN; ++p) {
        g_idx[base + p] = g * LG + bi[p];        // global node row
        g_w[base + p]   = expf(-10.0f * bd[p]);
    }
}

// ---------------------------------------------------------------------------
// Kernel 3: gather neighbors, weighted mean + max -> g_agg[N][128]
// thread = (node, feature). Warp spans 32 consecutive features -> coalesced.
// ---------------------------------------------------------------------------
__global__ __launch_bounds__(256) void k3_agg()
{
    const int t = blockIdx.x * 256 + threadIdx.x;   // t < NTOT*FLR
    const int n = t >> 6;
    const int f = t & 63;

    const int*   ip = g_idx + (size_t)n * KNN;
    const float* wp = g_w   + (size_t)n * KNN;

    float sum = 0.0f, mx = -CUDART_INF_F;
    #pragma unroll
    for (int k = 0; k < KNN; ++k) {
        const int j = ip[k];
        const float v = g_h[(size_t)j * FLR + f] * wp[k];
        sum += v;
        mx = fmaxf(mx, v);
    }
    g_agg[(size_t)n * (2 * FLR) + f]       = sum * (1.0f / (float)KNN);
    g_agg[(size_t)n * (2 * FLR) + FLR + f] = mx;
}

// ---------------------------------------------------------------------------
// Kernel 4: out = relu([x ‖ agg] @ W_out + b_out)
// Tiled fp32 SGEMM: 128x128 block tile, BK=16, 8x8 per thread.
// ---------------------------------------------------------------------------
__global__ __launch_bounds__(256) void k4_gemm(
    const float* __restrict__ x,
    const float* __restrict__ Wo, const float* __restrict__ bo,
    float* __restrict__ out)
{
    __shared__ float As[16][128];   // transposed: As[k][m]
    __shared__ float Bs[16][128];   // Bs[k][n]

    const int tid = threadIdx.x;
    const int tm  = tid >> 4;       // 0..15
    const int tn  = tid & 15;       // 0..15
    const int row0 = blockIdx.x * 128;

    float acc[8][8];
    #pragma unroll
    for (int i = 0; i < 8; ++i)
        #pragma unroll
        for (int j = 0; j < 8; ++j) acc[i][j] = 0.0f;

    for (int kt = 0; kt < 16; ++kt) {           // K = 256 total, BK = 16
        const int kbase = kt * 16;
        const float* Asrc = (kbase < FIN)
            ? (x     + (size_t)row0 * FIN + kbase)
            : (g_agg + (size_t)row0 * (2 * FLR) + (kbase - FIN));

        // A tile: 128 rows x 16 k  (2 float4 per thread), store transposed
        #pragma unroll
        for (int i = 0; i < 2; ++i) {
            const int e  = tid * 2 + i;         // 0..511
            const int r  = e >> 2;
            const int c4 = (e & 3) * 4;
            const float4 v = *(const float4*)(Asrc + (size_t)r * FIN + c4);
            As[c4 + 0][r] = v.x; As[c4 + 1][r] = v.y;
            As[c4 + 2][r] = v.z; As[c4 + 3][r] = v.w;
        }
        // B tile: 16 k-rows x 128 cols of W_out
        #pragma unroll
        for (int i = 0; i < 2; ++i) {
            const int e  = tid * 2 + i;         // 0..511
            const int r  = e >> 5;
            const int c4 = (e & 31) * 4;
            *(float4*)&Bs[r][c4] = *(const float4*)(Wo + (size_t)(kbase + r) * FOUT + c4);
        }
        __syncthreads();

        #pragma unroll
        for (int k = 0; k < 16; ++k) {
            float a[8], b[8];
            *(float4*)&a[0] = *(float4*)&As[k][tm * 8];
            *(float4*)&a[4] = *(float4*)&As[k][tm * 8 + 4];
            *(float4*)&b[0] = *(float4*)&Bs[k][tn * 8];
            *(float4*)&b[4] = *(float4*)&Bs[k][tn * 8 + 4];
            #pragma unroll
            for (int i = 0; i < 8; ++i)
                #pragma unroll
                for (int j = 0; j < 8; ++j)
                    acc[i][j] += a[i] * b[j];
        }
        __syncthreads();
    }

    // Epilogue: bias + ReLU, vectorized stores
    #pragma unroll
    for (int i = 0; i < 8; ++i) {
        const int row = row0 + tm * 8 + i;
        #pragma unroll
        for (int j = 0; j < 8; j += 4) {
            const int col = tn * 8 + j;
            float4 v;
            v.x = fmaxf(acc[i][j + 0] + bo[col + 0], 0.0f);
            v.y = fmaxf(acc[i][j + 1] + bo[col + 1], 0.0f);
            v.z = fmaxf(acc[i][j + 2] + bo[col + 2], 0.0f);
            v.w = fmaxf(acc[i][j + 3] + bo[col + 3], 0.0f);
            *(float4*)(out + (size_t)row * FOUT + col) = v;
        }
    }
}

// ---------------------------------------------------------------------------
// Launch
// Inputs (metadata order): x, W_s, b_s, W_h, b_h, W_out, b_out, batch(int64)
// ---------------------------------------------------------------------------
extern "C" void kernel_launch(void* const* d_in, const int* in_sizes, int n_in,
                              void* d_out, int out_size)
{
    const float* x   = (const float*)d_in[0];
    const float* Ws  = (const float*)d_in[1];
    const float* bs  = (const float*)d_in[2];
    const float* Wh  = (const float*)d_in[3];
    const float* bh  = (const float*)d_in[4];
    const float* Wo  = (const float*)d_in[5];
    const float* bo  = (const float*)d_in[6];
    // d_in[7] = batch (int64) — graphs are contiguous & equal-size, unused.
    float* out = (float*)d_out;

    k1_embed<<<NTOT / 16, 256>>>(x, Ws, bs, Wh, bh);
    k2_knn<<<dim3(LG / 256, BG), 256>>>();
    k3_agg<<<(NTOT * FLR) / 256, 256>>>();
    k4_gemm<<<NTOT / 128, 256>>>(x, Wo, bo, out);
}

// round 2
// speedup vs baseline: 1.4223x; 1.4223x over previous
#include <cuda_runtime.h>
#include <math_constants.h>

// Problem constants (fixed shapes)
#define BG   64      // graphs
#define LG   1024    // nodes per graph
#define KNN  16      // neighbors
#define FIN  128     // in features
#define FOUT 128     // out features
#define SDIM 4       // space dims
#define FLR  64      // propagate dims
#define NTOT (BG*LG) // 65536

// Scratch (static device arrays — no allocation)
__device__ float g_s[NTOT * SDIM];          // 1 MB
__device__ float g_h[NTOT * FLR];           // 16 MB
__device__ int   g_idx[NTOT * KNN];         // 4 MB
__device__ float g_w[NTOT * KNN];           // 4 MB
__device__ float g_agg[NTOT * 2 * FLR];     // 32 MB  (mean ‖ max)

// ---------------------------------------------------------------------------
// Kernel 1s: s = x@W_s + b_s   (64 nodes/block staged in shared, W in shared)
// ---------------------------------------------------------------------------
__global__ __launch_bounds__(256) void k1s_embed(
    const float* __restrict__ x,
    const float* __restrict__ Ws, const float* __restrict__ bs)
{
    __shared__ float xs[64][FIN];     // 32 KB
    __shared__ float sw[FIN][SDIM];   // 2 KB
    __shared__ float sb[SDIM];

    const int n0 = blockIdx.x * 64;

    // stage 64 x rows (8192 floats = 2048 float4)
    const float4* xg  = (const float4*)(x + (size_t)n0 * FIN);
    float4*       xs4 = (float4*)&xs[0][0];
    for (int i = threadIdx.x; i < 2048; i += 256) xs4[i] = xg[i];
    // stage W_s (512 floats) + bias
    for (int i = threadIdx.x; i < FIN * SDIM; i += 256) ((float*)sw)[i] = Ws[i];
    if (threadIdx.x < SDIM) sb[threadIdx.x] = bs[threadIdx.x];
    __syncthreads();

    const int nl = threadIdx.x >> 2;   // 0..63
    const int j  = threadIdx.x & 3;    // 0..3
    float acc = sb[j];
    #pragma unroll 16
    for (int k = 0; k < FIN; ++k) acc += xs[nl][k] * sw[k][j];
    g_s[(size_t)(n0 + nl) * SDIM + j] = acc;
}

// ---------------------------------------------------------------------------
// Kernel 1h: h = x@W_h + b_h   (tiled SGEMM: 128x64 tile, BK=16, 4x8 regs)
// ---------------------------------------------------------------------------
__global__ __launch_bounds__(256) void k1h_embed(
    const float* __restrict__ x,
    const float* __restrict__ Wh, const float* __restrict__ bh)
{
    __shared__ float As[16][128];   // transposed: As[k][m]
    __shared__ float Bs[16][64];    // Bs[k][n]

    const int tid  = threadIdx.x;
    const int tm   = tid >> 3;      // 0..31 -> 4 rows each
    const int tn   = tid & 7;       // 0..7  -> 8 cols each
    const int row0 = blockIdx.x * 128;

    float acc[4][8];
    #pragma unroll
    for (int i = 0; i < 4; ++i)
        #pragma unroll
        for (int j = 0; j < 8; ++j) acc[i][j] = 0.0f;

    for (int kt = 0; kt < FIN / 16; ++kt) {
        const int kbase = kt * 16;

        // A tile: 128 rows x 16 k (2 float4/thread), stored transposed
        #pragma unroll
        for (int i = 0; i < 2; ++i) {
            const int e  = tid * 2 + i;           // 0..511
            const int r  = e >> 2;                // 0..127
            const int c4 = (e & 3) * 4;           // 0,4,8,12
            const float4 v = *(const float4*)(x + (size_t)(row0 + r) * FIN + kbase + c4);
            As[c4 + 0][r] = v.x; As[c4 + 1][r] = v.y;
            As[c4 + 2][r] = v.z; As[c4 + 3][r] = v.w;
        }
        // B tile: 16 k-rows x 64 cols (1 float4/thread)
        {
            const int r  = tid >> 4;              // 0..15
            const int c4 = (tid & 15) * 4;        // 0..60
            *(float4*)&Bs[r][c4] = *(const float4*)(Wh + (size_t)(kbase + r) * FLR + c4);
        }
        __syncthreads();

        #pragma unroll
        for (int k = 0; k < 16; ++k) {
            float a[4], b[8];
            *(float4*)&a[0] = *(float4*)&As[k][tm * 4];
            *(float4*)&b[0] = *(float4*)&Bs[k][tn * 8];
            *(float4*)&b[4] = *(float4*)&Bs[k][tn * 8 + 4];
            #pragma unroll
            for (int i = 0; i < 4; ++i)
                #pragma unroll
                for (int j = 0; j < 8; ++j)
                    acc[i][j] += a[i] * b[j];
        }
        __syncthreads();
    }

    #pragma unroll
    for (int i = 0; i < 4; ++i) {
        const int row = row0 + tm * 4 + i;
        #pragma unroll
        for (int j = 0; j < 8; j += 4) {
            const int col = tn * 8 + j;
            float4 v;
            v.x = acc[i][j + 0] + bh[col + 0];
            v.y = acc[i][j + 1] + bh[col + 1];
            v.z = acc[i][j + 2] + bh[col + 2];
            v.w = acc[i][j + 3] + bh[col + 3];
            *(float4*)(g_h + (size_t)row * FLR + col) = v;
        }
    }
}

// ---------------------------------------------------------------------------
// Kernel 2: per-graph kNN (top-16 smallest d2) + edge weights exp(-10 d2)
// Ranks by score = sq[j] - 2*dot (monotone in d2). Branchless predicated
// 16-step insertion; clamp applied only to final winners.
// ---------------------------------------------------------------------------
__global__ __launch_bounds__(256) void k2_knn()
{
    __shared__ float4 ss[LG];
    __shared__ float  sqs[LG];

    const int g  = blockIdx.y;
    const int q0 = blockIdx.x * 256;

    const float4* sg4 = (const float4*)(g_s + (size_t)g * LG * SDIM);
    for (int i = threadIdx.x; i < LG; i += 256) {
        float4 v = sg4[i];
        ss[i]  = v;
        sqs[i] = ((v.x * v.x + v.y * v.y) + v.z * v.z) + v.w * v.w;
    }
    __syncthreads();

    const int q = q0 + threadIdx.x;
    const float4 si  = ss[q];
    const float  sqi = sqs[q];

    float bd[KNN];   // scores, sorted ascending
    int   bi[KNN];
    #pragma unroll
    for (int p = 0; p < KNN; ++p) { bd[p] = CUDART_INF_F; bi[p] = -1; }

    #pragma unroll 4
    for (int j = 0; j < LG; ++j) {
        const float4 sj = ss[j];
        const float dot = ((si.x * sj.x + si.y * sj.y) + si.z * sj.z) + si.w * sj.w;
        const float sc  = fmaf(-2.0f, dot, sqs[j]);   // score = sq[j] - 2*dot
        if (sc < bd[KNN - 1]) {
            float cd = sc; int ci = j;
            #pragma unroll
            for (int p = 0; p < KNN; ++p) {
                const bool sw = cd < bd[p];
                const float nd = sw ? bd[p] : cd;
                const int   ni = sw ? bi[p] : ci;
                bd[p] = sw ? cd : bd[p];
                bi[p] = sw ? ci : bi[p];
                cd = nd; ci = ni;
            }
        }
    }

    const size_t base = (size_t)(g * LG + q) * KNN;
    #pragma unroll
    for (int p = 0; p < KNN; ++p) {
        const float d2 = fmaxf(sqi + bd[p], 0.0f);
        g_idx[base + p] = g * LG + bi[p];        // global node row
        g_w[base + p]   = expf(-10.0f * d2);
    }
}

// ---------------------------------------------------------------------------
// Kernel 3: gather neighbors, weighted mean + max -> g_agg[N][128]
// ---------------------------------------------------------------------------
__global__ __launch_bounds__(256) void k3_agg()
{
    const int t = blockIdx.x * 256 + threadIdx.x;   // t < NTOT*FLR
    const int n = t >> 6;
    const int f = t & 63;

    const int*   ip = g_idx + (size_t)n * KNN;
    const float* wp = g_w   + (size_t)n * KNN;

    float sum = 0.0f, mx = -CUDART_INF_F;
    #pragma unroll
    for (int k = 0; k < KNN; ++k) {
        const int j = ip[k];
        const float v = g_h[(size_t)j * FLR + f] * wp[k];
        sum += v;
        mx = fmaxf(mx, v);
    }
    g_agg[(size_t)n * (2 * FLR) + f]       = sum * (1.0f / (float)KNN);
    g_agg[(size_t)n * (2 * FLR) + FLR + f] = mx;
}

// ---------------------------------------------------------------------------
// Kernel 4: out = relu([x ‖ agg] @ W_out + b_out)
// Tiled fp32 SGEMM: 128x128 block tile, BK=16, 8x8 per thread.
// ---------------------------------------------------------------------------
__global__ __launch_bounds__(256) void k4_gemm(
    const float* __restrict__ x,
    const float* __restrict__ Wo, const float* __restrict__ bo,
    float* __restrict__ out)
{
    __shared__ float As[16][128];   // transposed: As[k][m]
    __shared__ float Bs[16][128];   // Bs[k][n]

    const int tid = threadIdx.x;
    const int tm  = tid >> 4;       // 0..15
    const int tn  = tid & 15;       // 0..15
    const int row0 = blockIdx.x * 128;

    float acc[8][8];
    #pragma unroll
    for (int i = 0; i < 8; ++i)
        #pragma unroll
        for (int j = 0; j < 8; ++j) acc[i][j] = 0.0f;

    for (int kt = 0; kt < 16; ++kt) {           // K = 256 total, BK = 16
        const int kbase = kt * 16;
        const float* Asrc = (kbase < FIN)
            ? (x     + (size_t)row0 * FIN + kbase)
            : (g_agg + (size_t)row0 * (2 * FLR) + (kbase - FIN));

        // A tile: 128 rows x 16 k  (2 float4 per thread), store transposed
        #pragma unroll
        for (int i = 0; i < 2; ++i) {
            const int e  = tid * 2 + i;         // 0..511
            const int r  = e >> 2;
            const int c4 = (e & 3) * 4;
            const float4 v = *(const float4*)(Asrc + (size_t)r * FIN + c4);
            As[c4 + 0][r] = v.x; As[c4 + 1][r] = v.y;
            As[c4 + 2][r] = v.z; As[c4 + 3][r] = v.w;
        }
        // B tile: 16 k-rows x 128 cols of W_out
        #pragma unroll
        for (int i = 0; i < 2; ++i) {
            const int e  = tid * 2 + i;         // 0..511
            const int r  = e >> 5;
            const int c4 = (e & 31) * 4;
            *(float4*)&Bs[r][c4] = *(const float4*)(Wo + (size_t)(kbase + r) * FOUT + c4);
        }
        __syncthreads();

        #pragma unroll
        for (int k = 0; k < 16; ++k) {
            float a[8], b[8];
            *(float4*)&a[0] = *(float4*)&As[k][tm * 8];
            *(float4*)&a[4] = *(float4*)&As[k][tm * 8 + 4];
            *(float4*)&b[0] = *(float4*)&Bs[k][tn * 8];
            *(float4*)&b[4] = *(float4*)&Bs[k][tn * 8 + 4];
            #pragma unroll
            for (int i = 0; i < 8; ++i)
                #pragma unroll
                for (int j = 0; j < 8; ++j)
                    acc[i][j] += a[i] * b[j];
        }
        __syncthreads();
    }

    // Epilogue: bias + ReLU, vectorized stores
    #pragma unroll
    for (int i = 0; i < 8; ++i) {
        const int row = row0 + tm * 8 + i;
        #pragma unroll
        for (int j = 0; j < 8; j += 4) {
            const int col = tn * 8 + j;
            float4 v;
            v.x = fmaxf(acc[i][j + 0] + bo[col + 0], 0.0f);
            v.y = fmaxf(acc[i][j + 1] + bo[col + 1], 0.0f);
            v.z = fmaxf(acc[i][j + 2] + bo[col + 2], 0.0f);
            v.w = fmaxf(acc[i][j + 3] + bo[col + 3], 0.0f);
            *(float4*)(out + (size_t)row * FOUT + col) = v;
        }
    }
}

// ---------------------------------------------------------------------------
// Launch
// Inputs (metadata order): x, W_s, b_s, W_h, b_h, W_out, b_out, batch(int64)
// ---------------------------------------------------------------------------
extern "C" void kernel_launch(void* const* d_in, const int* in_sizes, int n_in,
                              void* d_out, int out_size)
{
    const float* x   = (const float*)d_in[0];
    const float* Ws  = (const float*)d_in[1];
    const float* bs  = (const float*)d_in[2];
    const float* Wh  = (const float*)d_in[3];
    const float* bh  = (const float*)d_in[4];
    const float* Wo  = (const float*)d_in[5];
    const float* bo  = (const float*)d_in[6];
    // d_in[7] = batch (int64) — graphs are contiguous & equal-size, unused.
    float* out = (float*)d_out;

    k1s_embed<<<NTOT / 64, 256>>>(x, Ws, bs);
    k1h_embed<<<NTOT / 128, 256>>>(x, Wh, bh);
    k2_knn<<<dim3(LG / 256, BG), 256>>>();
    k3_agg<<<(NTOT * FLR) / 256, 256>>>();
    k4_gemm<<<NTOT / 128, 256>>>(x, Wo, bo, out);
}

// round 4
// speedup vs baseline: 1.9078x; 1.3414x over previous
#include <cuda_runtime.h>
#include <math_constants.h>

// Problem constants (fixed shapes)
#define BG   64      // graphs
#define LG   1024    // nodes per graph
#define KNN  16      // neighbors
#define FIN  128     // in features
#define FOUT 128     // out features
#define SDIM 4       // space dims
#define FLR  64      // propagate dims
#define NTOT (BG*LG) // 65536

// Scratch (static device arrays — no allocation)
__device__ float g_s[NTOT * SDIM];          // 1 MB
__device__ float g_h[NTOT * FLR];           // 16 MB
__device__ int   g_idx[NTOT * KNN];         // 4 MB
__device__ float g_w[NTOT * KNN];           // 4 MB
__device__ float g_agg[NTOT * 2 * FLR];     // 32 MB  (mean ‖ max)

// ---------------------------------------------------------------------------
// Kernel 1s: s = x@W_s + b_s   (64 nodes/block staged in shared, W in shared)
// ---------------------------------------------------------------------------
__global__ __launch_bounds__(256) void k1s_embed(
    const float* __restrict__ x,
    const float* __restrict__ Ws, const float* __restrict__ bs)
{
    __shared__ float xs[64][FIN];     // 32 KB
    __shared__ float sw[FIN][SDIM];   // 2 KB
    __shared__ float sb[SDIM];

    const int n0 = blockIdx.x * 64;

    const float4* xg  = (const float4*)(x + (size_t)n0 * FIN);
    float4*       xs4 = (float4*)&xs[0][0];
    for (int i = threadIdx.x; i < 2048; i += 256) xs4[i] = xg[i];
    for (int i = threadIdx.x; i < FIN * SDIM; i += 256) ((float*)sw)[i] = Ws[i];
    if (threadIdx.x < SDIM) sb[threadIdx.x] = bs[threadIdx.x];
    __syncthreads();

    const int nl = threadIdx.x >> 2;   // 0..63
    const int j  = threadIdx.x & 3;    // 0..3
    float acc = sb[j];
    #pragma unroll 16
    for (int k = 0; k < FIN; ++k) acc += xs[nl][k] * sw[k][j];
    g_s[(size_t)(n0 + nl) * SDIM + j] = acc;
}

// ---------------------------------------------------------------------------
// Kernel 1h: h = x@W_h + b_h   (tiled SGEMM: 128x64 tile, BK=16, 4x8 regs)
// ---------------------------------------------------------------------------
__global__ __launch_bounds__(256) void k1h_embed(
    const float* __restrict__ x,
    const float* __restrict__ Wh, const float* __restrict__ bh)
{
    __shared__ float As[16][128];   // transposed: As[k][m]
    __shared__ float Bs[16][64];    // Bs[k][n]

    const int tid  = threadIdx.x;
    const int tm   = tid >> 3;      // 0..31 -> 4 rows each
    const int tn   = tid & 7;       // 0..7  -> 8 cols each
    const int row0 = blockIdx.x * 128;

    float acc[4][8];
    #pragma unroll
    for (int i = 0; i < 4; ++i)
        #pragma unroll
        for (int j = 0; j < 8; ++j) acc[i][j] = 0.0f;

    for (int kt = 0; kt < FIN / 16; ++kt) {
        const int kbase = kt * 16;

        #pragma unroll
        for (int i = 0; i < 2; ++i) {
            const int e  = tid * 2 + i;           // 0..511
            const int r  = e >> 2;                // 0..127
            const int c4 = (e & 3) * 4;           // 0,4,8,12
            const float4 v = *(const float4*)(x + (size_t)(row0 + r) * FIN + kbase + c4);
            As[c4 + 0][r] = v.x; As[c4 + 1][r] = v.y;
            As[c4 + 2][r] = v.z; As[c4 + 3][r] = v.w;
        }
        {
            const int r  = tid >> 4;              // 0..15
            const int c4 = (tid & 15) * 4;        // 0..60
            *(float4*)&Bs[r][c4] = *(const float4*)(Wh + (size_t)(kbase + r) * FLR + c4);
        }
        __syncthreads();

        #pragma unroll
        for (int k = 0; k < 16; ++k) {
            float a[4], b[8];
            *(float4*)&a[0] = *(float4*)&As[k][tm * 4];
            *(float4*)&b[0] = *(float4*)&Bs[k][tn * 8];
            *(float4*)&b[4] = *(float4*)&Bs[k][tn * 8 + 4];
            #pragma unroll
            for (int i = 0; i < 4; ++i)
                #pragma unroll
                for (int j = 0; j < 8; ++j)
                    acc[i][j] += a[i] * b[j];
        }
        __syncthreads();
    }

    #pragma unroll
    for (int i = 0; i < 4; ++i) {
        const int row = row0 + tm * 4 + i;
        #pragma unroll
        for (int j = 0; j < 8; j += 4) {
            const int col = tn * 8 + j;
            float4 v;
            v.x = acc[i][j + 0] + bh[col + 0];
            v.y = acc[i][j + 1] + bh[col + 1];
            v.z = acc[i][j + 2] + bh[col + 2];
            v.w = acc[i][j + 3] + bh[col + 3];
            *(float4*)(g_h + (size_t)row * FLR + col) = v;
        }
    }
}

// ---------------------------------------------------------------------------
// Kernel 2: per-graph kNN via filter-then-insert.
// Window of 64 candidates: branchless score scan sets bits in a uint64 mask
// for candidates beating the (window-stale) 16th-best; drain walks set bits,
// re-tests against the FRESH threshold, and runs the insertion chain only
// for true passers. Result identical to a direct scan (stale threshold only
// over-admits; drain processes bits in ascending j and re-filters strictly).
// ---------------------------------------------------------------------------
__global__ __launch_bounds__(128) void k2_knn()
{
    __shared__ float4 ss[LG];
    __shared__ float  sqs[LG];

    const int g  = blockIdx.y;
    const int q0 = blockIdx.x * 128;

    const float4* sg4 = (const float4*)(g_s + (size_t)g * LG * SDIM);
    for (int i = threadIdx.x; i < LG; i += 128) {
        float4 v = sg4[i];
        ss[i]  = v;
        sqs[i] = ((v.x * v.x + v.y * v.y) + v.z * v.z) + v.w * v.w;
    }
    __syncthreads();

    const int q = q0 + threadIdx.x;
    const float4 si  = ss[q];
    const float  sqi = sqs[q];

    float bd[KNN];   // scores, sorted ascending
    int   bi[KNN];
    #pragma unroll
    for (int p = 0; p < KNN; ++p) { bd[p] = CUDART_INF_F; bi[p] = -1; }

    for (int w = 0; w < LG; w += 64) {
        // -- scan phase: branchless, threshold frozen for the window --
        const float kmax = bd[KNN - 1];
        unsigned long long mask = 0ull;
        #pragma unroll
        for (int t = 0; t < 64; ++t) {
            const float4 sj = ss[w + t];
            const float dot = ((si.x * sj.x + si.y * sj.y) + si.z * sj.z) + si.w * sj.w;
            const float sc  = fmaf(-2.0f, dot, sqs[w + t]);   // sq[j] - 2*dot
            if (sc < kmax) mask |= (1ull << t);
        }
        // -- drain phase: only true candidates touch the chain --
        while (mask) {
            const int t = __ffsll((long long)mask) - 1;
            mask &= mask - 1ull;
            const int j = w + t;
            const float4 sj = ss[j];
            const float dot = ((si.x * sj.x + si.y * sj.y) + si.z * sj.z) + si.w * sj.w;
            const float sc  = fmaf(-2.0f, dot, sqs[j]);
            if (sc < bd[KNN - 1]) {
                float cd = sc; int ci = j;
                #pragma unroll
                for (int p = 0; p < KNN; ++p) {
                    const bool swp = cd < bd[p];   // strict < keeps stable order
                    const float nd = swp ? bd[p] : cd;
                    const int   ni = swp ? bi[p] : ci;
                    bd[p] = swp ? cd : bd[p];
                    bi[p] = swp ? ci : bi[p];
                    cd = nd; ci = ni;
                }
            }
        }
    }

    const size_t base = (size_t)(g * LG + q) * KNN;
    #pragma unroll
    for (int p = 0; p < KNN; ++p) {
        const float d2 = fmaxf(sqi + bd[p], 0.0f);
        g_idx[base + p] = g * LG + bi[p];        // global node row
        g_w[base + p]   = expf(-10.0f * d2);
    }
}

// ---------------------------------------------------------------------------
// Kernel 3: gather neighbors, weighted mean + max -> g_agg[N][128]
// ---------------------------------------------------------------------------
__global__ __launch_bounds__(256) void k3_agg()
{
    const int t = blockIdx.x * 256 + threadIdx.x;   // t < NTOT*FLR
    const int n = t >> 6;
    const int f = t & 63;

    const int*   ip = g_idx + (size_t)n * KNN;
    const float* wp = g_w   + (size_t)n * KNN;

    float sum = 0.0f, mx = -CUDART_INF_F;
    #pragma unroll
    for (int k = 0; k < KNN; ++k) {
        const int j = ip[k];
        const float v = g_h[(size_t)j * FLR + f] * wp[k];
        sum += v;
        mx = fmaxf(mx, v);
    }
    g_agg[(size_t)n * (2 * FLR) + f]       = sum * (1.0f / (float)KNN);
    g_agg[(size_t)n * (2 * FLR) + FLR + f] = mx;
}

// ---------------------------------------------------------------------------
// Kernel 4: out = relu([x ‖ agg] @ W_out + b_out)
// Tiled fp32 SGEMM: 128x128 block tile, BK=16, 8x8 per thread.
// ---------------------------------------------------------------------------
__global__ __launch_bounds__(256) void k4_gemm(
    const float* __restrict__ x,
    const float* __restrict__ Wo, const float* __restrict__ bo,
    float* __restrict__ out)
{
    __shared__ float As[16][128];   // transposed: As[k][m]
    __shared__ float Bs[16][128];   // Bs[k][n]

    const int tid = threadIdx.x;
    const int tm  = tid >> 4;       // 0..15
    const int tn  = tid & 15;       // 0..15
    const int row0 = blockIdx.x * 128;

    float acc[8][8];
    #pragma unroll
    for (int i = 0; i < 8; ++i)
        #pragma unroll
        for (int j = 0; j < 8; ++j) acc[i][j] = 0.0f;

    for (int kt = 0; kt < 16; ++kt) {           // K = 256 total, BK = 16
        const int kbase = kt * 16;
        const float* Asrc = (kbase < FIN)
            ? (x     + (size_t)row0 * FIN + kbase)
            : (g_agg + (size_t)row0 * (2 * FLR) + (kbase - FIN));

        #pragma unroll
        for (int i = 0; i < 2; ++i) {
            const int e  = tid * 2 + i;         // 0..511
            const int r  = e >> 2;
            const int c4 = (e & 3) * 4;
            const float4 v = *(const float4*)(Asrc + (size_t)r * FIN + c4);
            As[c4 + 0][r] = v.x; As[c4 + 1][r] = v.y;
            As[c4 + 2][r] = v.z; As[c4 + 3][r] = v.w;
        }
        #pragma unroll
        for (int i = 0; i < 2; ++i) {
            const int e  = tid * 2 + i;         // 0..511
            const int r  = e >> 5;
            const int c4 = (e & 31) * 4;
            *(float4*)&Bs[r][c4] = *(const float4*)(Wo + (size_t)(kbase + r) * FOUT + c4);
        }
        __syncthreads();

        #pragma unroll
        for (int k = 0; k < 16; ++k) {
            float a[8], b[8];
            *(float4*)&a[0] = *(float4*)&As[k][tm * 8];
            *(float4*)&a[4] = *(float4*)&As[k][tm * 8 + 4];
            *(float4*)&b[0] = *(float4*)&Bs[k][tn * 8];
            *(float4*)&b[4] = *(float4*)&Bs[k][tn * 8 + 4];
            #pragma unroll
            for (int i = 0; i < 8; ++i)
                #pragma unroll
                for (int j = 0; j < 8; ++j)
                    acc[i][j] += a[i] * b[j];
        }
        __syncthreads();
    }

    #pragma unroll
    for (int i = 0; i < 8; ++i) {
        const int row = row0 + tm * 8 + i;
        #pragma unroll
        for (int j = 0; j < 8; j += 4) {
            const int col = tn * 8 + j;
            float4 v;
            v.x = fmaxf(acc[i][j + 0] + bo[col + 0], 0.0f);
            v.y = fmaxf(acc[i][j + 1] + bo[col + 1], 0.0f);
            v.z = fmaxf(acc[i][j + 2] + bo[col + 2], 0.0f);
            v.w = fmaxf(acc[i][j + 3] + bo[col + 3], 0.0f);
            *(float4*)(out + (size_t)row * FOUT + col) = v;
        }
    }
}

// ---------------------------------------------------------------------------
// Launch
// Inputs (metadata order): x, W_s, b_s, W_h, b_h, W_out, b_out, batch(int64)
// ---------------------------------------------------------------------------
extern "C" void kernel_launch(void* const* d_in, const int* in_sizes, int n_in,
                              void* d_out, int out_size)
{
    const float* x   = (const float*)d_in[0];
    const float* Ws  = (const float*)d_in[1];
    const float* bs  = (const float*)d_in[2];
    const float* Wh  = (const float*)d_in[3];
    const float* bh  = (const float*)d_in[4];
    const float* Wo  = (const float*)d_in[5];
    const float* bo  = (const float*)d_in[6];
    // d_in[7] = batch (int64) — graphs are contiguous & equal-size, unused.
    float* out = (float*)d_out;

    k1s_embed<<<NTOT / 64, 256>>>(x, Ws, bs);
    k1h_embed<<<NTOT / 128, 256>>>(x, Wh, bh);
    k2_knn<<<dim3(LG / 128, BG), 128>>>();
    k3_agg<<<(NTOT * FLR) / 256, 256>>>();
    k4_gemm<<<NTOT / 128, 256>>>(x, Wo, bo, out);
}

// round 8
// speedup vs baseline: 2.0297x; 1.0639x over previous
#include <cuda_runtime.h>
#include <math_constants.h>

// Problem constants (fixed shapes)
#define BG   64      // graphs
#define LG   1024    // nodes per graph
#define KNN  16      // neighbors
#define FIN  128     // in features
#define FOUT 128     // out features
#define SDIM 4       // space dims
#define FLR  64      // propagate dims
#define NTOT (BG*LG) // 65536

// Scratch (static device arrays — no allocation)
__device__ float g_s[NTOT * SDIM];          // 1 MB
__device__ float g_h[NTOT * FLR];           // 16 MB
__device__ int   g_idx[NTOT * KNN];         // 4 MB
__device__ float g_w[NTOT * KNN];           // 4 MB
__device__ float g_agg[NTOT * 2 * FLR];     // 32 MB  (mean ‖ max)

// cp.async helpers (16B, GMEM -> SMEM, no registers)
__device__ __forceinline__ void cp_async16(void* smem_dst, const void* gsrc) {
    unsigned saddr = (unsigned)__cvta_generic_to_shared(smem_dst);
    asm volatile("cp.async.cg.shared.global [%0], [%1], 16;\n" :: "r"(saddr), "l"(gsrc));
}
__device__ __forceinline__ void cp_commit() {
    asm volatile("cp.async.commit_group;\n");
}
__device__ __forceinline__ void cp_wait0() {
    asm volatile("cp.async.wait_group 0;\n" ::: "memory");
}

// ---------------------------------------------------------------------------
// Kernel 1s: s = x@W_s + b_s   (64 nodes/block staged in shared, W in shared)
// ---------------------------------------------------------------------------
__global__ __launch_bounds__(256) void k1s_embed(
    const float* __restrict__ x,
    const float* __restrict__ Ws, const float* __restrict__ bs)
{
    __shared__ float xs[64][FIN];     // 32 KB
    __shared__ float sw[FIN][SDIM];   // 2 KB
    __shared__ float sb[SDIM];

    const int n0 = blockIdx.x * 64;

    const float4* xg  = (const float4*)(x + (size_t)n0 * FIN);
    float4*       xs4 = (float4*)&xs[0][0];
    for (int i = threadIdx.x; i < 2048; i += 256) xs4[i] = xg[i];
    for (int i = threadIdx.x; i < FIN * SDIM; i += 256) ((float*)sw)[i] = Ws[i];
    if (threadIdx.x < SDIM) sb[threadIdx.x] = bs[threadIdx.x];
    __syncthreads();

    const int nl = threadIdx.x >> 2;   // 0..63
    const int j  = threadIdx.x & 3;    // 0..3
    float acc = sb[j];
    #pragma unroll 16
    for (int k = 0; k < FIN; ++k) acc += xs[nl][k] * sw[k][j];
    g_s[(size_t)(n0 + nl) * SDIM + j] = acc;
}

// ---------------------------------------------------------------------------
// Kernel 1h: h = x@W_h + b_h   (tiled SGEMM: 128x64 tile, BK=16, 4x8 regs)
// ---------------------------------------------------------------------------
__global__ __launch_bounds__(256) void k1h_embed(
    const float* __restrict__ x,
    const float* __restrict__ Wh, const float* __restrict__ bh)
{
    __shared__ float As[16][128];   // transposed: As[k][m]
    __shared__ float Bs[16][64];    // Bs[k][n]

    const int tid  = threadIdx.x;
    const int tm   = tid >> 3;      // 0..31 -> 4 rows each
    const int tn   = tid & 7;       // 0..7  -> 8 cols each
    const int row0 = blockIdx.x * 128;

    float acc[4][8];
    #pragma unroll
    for (int i = 0; i < 4; ++i)
        #pragma unroll
        for (int j = 0; j < 8; ++j) acc[i][j] = 0.0f;

    for (int kt = 0; kt < FIN / 16; ++kt) {
        const int kbase = kt * 16;

        #pragma unroll
        for (int i = 0; i < 2; ++i) {
            const int e  = tid * 2 + i;           // 0..511
            const int r  = e >> 2;                // 0..127
            const int c4 = (e & 3) * 4;           // 0,4,8,12
            const float4 v = *(const float4*)(x + (size_t)(row0 + r) * FIN + kbase + c4);
            As[c4 + 0][r] = v.x; As[c4 + 1][r] = v.y;
            As[c4 + 2][r] = v.z; As[c4 + 3][r] = v.w;
        }
        {
            const int r  = tid >> 4;              // 0..15
            const int c4 = (tid & 15) * 4;        // 0..60
            *(float4*)&Bs[r][c4] = *(const float4*)(Wh + (size_t)(kbase + r) * FLR + c4);
        }
        __syncthreads();

        #pragma unroll
        for (int k = 0; k < 16; ++k) {
            float a[4], b[8];
            *(float4*)&a[0] = *(float4*)&As[k][tm * 4];
            *(float4*)&b[0] = *(float4*)&Bs[k][tn * 8];
            *(float4*)&b[4] = *(float4*)&Bs[k][tn * 8 + 4];
            #pragma unroll
            for (int i = 0; i < 4; ++i)
                #pragma unroll
                for (int j = 0; j < 8; ++j)
                    acc[i][j] += a[i] * b[j];
        }
        __syncthreads();
    }

    #pragma unroll
    for (int i = 0; i < 4; ++i) {
        const int row = row0 + tm * 4 + i;
        #pragma unroll
        for (int j = 0; j < 8; j += 4) {
            const int col = tn * 8 + j;
            float4 v;
            v.x = acc[i][j + 0] + bh[col + 0];
            v.y = acc[i][j + 1] + bh[col + 1];
            v.z = acc[i][j + 2] + bh[col + 2];
            v.w = acc[i][j + 3] + bh[col + 3];
            *(float4*)(g_h + (size_t)row * FLR + col) = v;
        }
    }
}

// ---------------------------------------------------------------------------
// Kernel 2: per-graph kNN via filter-then-insert.
// Shared holds m = -2*s so score = sq[j] + dot(s_q, m_j) is a pure 4-FFMA
// chain. Window of 64: branchless scan builds a uint64 candidate mask vs the
// window-stale threshold; drain re-tests against the fresh threshold and runs
// the sorted insertion chain only for true passers (result identical).
// ---------------------------------------------------------------------------
__global__ __launch_bounds__(128) void k2_knn()
{
    __shared__ float4 ss[LG];     // -2 * s
    __shared__ float  sqs[LG];    // |s|^2

    const int g  = blockIdx.y;
    const int q0 = blockIdx.x * 128;

    const float4* sg4 = (const float4*)(g_s + (size_t)g * LG * SDIM);
    for (int i = threadIdx.x; i < LG; i += 128) {
        float4 v = sg4[i];
        sqs[i] = ((v.x * v.x + v.y * v.y) + v.z * v.z) + v.w * v.w;
        v.x *= -2.0f; v.y *= -2.0f; v.z *= -2.0f; v.w *= -2.0f;
        ss[i]  = v;
    }
    __syncthreads();

    const int q = q0 + threadIdx.x;
    const float4 si  = sg4[q];                   // original s_q (from L2)
    const float  sqi = ((si.x * si.x + si.y * si.y) + si.z * si.z) + si.w * si.w;

    float bd[KNN];   // scores = sq[j] - 2*dot, sorted ascending
    int   bi[KNN];
    #pragma unroll
    for (int p = 0; p < KNN; ++p) { bd[p] = CUDART_INF_F; bi[p] = -1; }

    for (int w = 0; w < LG; w += 64) {
        // -- scan phase: branchless, threshold frozen for the window --
        const float kmax = bd[KNN - 1];
        unsigned long long mask = 0ull;
        #pragma unroll
        for (int t = 0; t < 64; ++t) {
            const float4 mj = ss[w + t];
            float sc = fmaf(si.x, mj.x, sqs[w + t]);
            sc = fmaf(si.y, mj.y, sc);
            sc = fmaf(si.z, mj.z, sc);
            sc = fmaf(si.w, mj.w, sc);
            if (sc < kmax) mask |= (1ull << t);
        }
        // -- drain phase: only true candidates touch the chain --
        while (mask) {
            const int t = __ffsll((long long)mask) - 1;
            mask &= mask - 1ull;
            const int j = w + t;
            const float4 mj = ss[j];
            float sc = fmaf(si.x, mj.x, sqs[j]);
            sc = fmaf(si.y, mj.y, sc);
            sc = fmaf(si.z, mj.z, sc);
            sc = fmaf(si.w, mj.w, sc);
            if (sc < bd[KNN - 1]) {
                float cd = sc; int ci = j;
                #pragma unroll
                for (int p = 0; p < KNN; ++p) {
                    const bool swp = cd < bd[p];   // strict < keeps stable order
                    const float nd = swp ? bd[p] : cd;
                    const int   ni = swp ? bi[p] : ci;
                    bd[p] = swp ? cd : bd[p];
                    bi[p] = swp ? ci : bi[p];
                    cd = nd; ci = ni;
                }
            }
        }
    }

    const size_t base = (size_t)(g * LG + q) * KNN;
    #pragma unroll
    for (int p = 0; p < KNN; ++p) {
        const float d2 = fmaxf(sqi + bd[p], 0.0f);
        g_idx[base + p] = g * LG + bi[p];        // global node row
        g_w[base + p]   = expf(-10.0f * d2);
    }
}

// ---------------------------------------------------------------------------
// Kernel 3: gather neighbors, weighted mean + max -> g_agg[N][128]
// 16 nodes per block; idx/w staged once in shared; float4 feature gathers.
// ---------------------------------------------------------------------------
__global__ __launch_bounds__(256) void k3_agg()
{
    __shared__ int   sidx[16][KNN];
    __shared__ float swt [16][KNN];

    const int n0 = blockIdx.x * 16;
    {
        const int e = threadIdx.x;           // 0..255 = 16 nodes x 16 nbrs
        const int n = e >> 4, k = e & 15;
        sidx[n][k] = g_idx[(size_t)(n0 + n) * KNN + k];
        swt[n][k]  = g_w  [(size_t)(n0 + n) * KNN + k];
    }
    __syncthreads();

    const int nl = threadIdx.x >> 4;          // 0..15 node within block
    const int f4 = (threadIdx.x & 15) * 4;    // feature group 0..60

    float4 sum = make_float4(0.f, 0.f, 0.f, 0.f);
    float4 mx  = make_float4(-CUDART_INF_F, -CUDART_INF_F, -CUDART_INF_F, -CUDART_INF_F);

    #pragma unroll
    for (int k = 0; k < KNN; ++k) {
        const int   j   = sidx[nl][k];
        const float wgt = swt[nl][k];
        float4 v = *(const float4*)(g_h + (size_t)j * FLR + f4);
        v.x *= wgt; v.y *= wgt; v.z *= wgt; v.w *= wgt;
        sum.x += v.x; sum.y += v.y; sum.z += v.z; sum.w += v.w;
        mx.x = fmaxf(mx.x, v.x); mx.y = fmaxf(mx.y, v.y);
        mx.z = fmaxf(mx.z, v.z); mx.w = fmaxf(mx.w, v.w);
    }

    const int n = n0 + nl;
    const float inv = 1.0f / (float)KNN;
    sum.x *= inv; sum.y *= inv; sum.z *= inv; sum.w *= inv;
    *(float4*)(g_agg + (size_t)n * (2 * FLR) + f4)       = sum;
    *(float4*)(g_agg + (size_t)n * (2 * FLR) + FLR + f4) = mx;
}

// ---------------------------------------------------------------------------
// Kernel 4: out = relu([x ‖ agg] @ W_out + b_out)
// 128x128 tile, BK=16, 8x8/thread. Double-buffered: B via cp.async,
// A register-staged (transposed), one __syncthreads per K-step.
// ---------------------------------------------------------------------------
__global__ __launch_bounds__(256) void k4_gemm(
    const float* __restrict__ x,
    const float* __restrict__ Wo, const float* __restrict__ bo,
    float* __restrict__ out)
{
    __shared__ float As[2][16][128];   // transposed: As[buf][k][m]
    __shared__ float Bs[2][16][128];   // Bs[buf][k][n]

    const int tid = threadIdx.x;
    const int tm  = tid >> 4;       // 0..15
    const int tn  = tid & 15;       // 0..15
    const int row0 = blockIdx.x * 128;

    // A-load geometry: row ar, cols acb..acb+7 of the 16-wide k-slice
    const int ar  = tid >> 1;           // 0..127
    const int acb = (tid & 1) * 8;      // 0 or 8
    // B-load geometry: row rB, cols cB..cB+7
    const int rB  = tid >> 4;           // 0..15
    const int cB  = (tid & 15) * 8;     // 0..120

    float4 a0, a1;                      // staged A fragment

    float acc[8][8];
    #pragma unroll
    for (int i = 0; i < 8; ++i)
        #pragma unroll
        for (int j = 0; j < 8; ++j) acc[i][j] = 0.0f;

    // ---- prologue: tile 0 ----
    {
        const float* src = x + (size_t)(row0 + ar) * FIN;   // kbase = 0
        a0 = *(const float4*)(src + acb);
        a1 = *(const float4*)(src + acb + 4);
        cp_async16(&Bs[0][rB][cB],     Wo + (size_t)rB * FOUT + cB);
        cp_async16(&Bs[0][rB][cB + 4], Wo + (size_t)rB * FOUT + cB + 4);
        cp_commit();
        As[0][acb + 0][ar] = a0.x; As[0][acb + 1][ar] = a0.y;
        As[0][acb + 2][ar] = a0.z; As[0][acb + 3][ar] = a0.w;
        As[0][acb + 4][ar] = a1.x; As[0][acb + 5][ar] = a1.y;
        As[0][acb + 6][ar] = a1.z; As[0][acb + 7][ar] = a1.w;
    }
    cp_wait0();
    __syncthreads();

    for (int kt = 0; kt < 16; ++kt) {           // K = 256, BK = 16
        const int cur = kt & 1, nxt = cur ^ 1;

        if (kt < 15) {
            const int kb = (kt + 1) * 16;
            const float* src = (kb < FIN)
                ? (x     + (size_t)(row0 + ar) * FIN + kb)
                : (g_agg + (size_t)(row0 + ar) * (2 * FLR) + (kb - FIN));
            a0 = *(const float4*)(src + acb);
            a1 = *(const float4*)(src + acb + 4);
            cp_async16(&Bs[nxt][rB][cB],     Wo + (size_t)(kb + rB) * FOUT + cB);
            cp_async16(&Bs[nxt][rB][cB + 4], Wo + (size_t)(kb + rB) * FOUT + cB + 4);
            cp_commit();
        }

        #pragma unroll
        for (int k = 0; k < 16; ++k) {
            float a[8], b[8];
            *(float4*)&a[0] = *(float4*)&As[cur][k][tm * 8];
            *(float4*)&a[4] = *(float4*)&As[cur][k][tm * 8 + 4];
            *(float4*)&b[0] = *(float4*)&Bs[cur][k][tn * 8];
            *(float4*)&b[4] = *(float4*)&Bs[cur][k][tn * 8 + 4];
            #pragma unroll
            for (int i = 0; i < 8; ++i)
                #pragma unroll
                for (int j = 0; j < 8; ++j)
                    acc[i][j] += a[i] * b[j];
        }

        if (kt < 15) {
            As[nxt][acb + 0][ar] = a0.x; As[nxt][acb + 1][ar] = a0.y;
            As[nxt][acb + 2][ar] = a0.z; As[nxt][acb + 3][ar] = a0.w;
            As[nxt][acb + 4][ar] = a1.x; As[nxt][acb + 5][ar] = a1.y;
            As[nxt][acb + 6][ar] = a1.z; As[nxt][acb + 7][ar] = a1.w;
            cp_wait0();
        }
        __syncthreads();
    }

    // Epilogue: bias + ReLU, vectorized stores
    #pragma unroll
    for (int i = 0; i < 8; ++i) {
        const int row = row0 + tm * 8 + i;
        #pragma unroll
        for (int j = 0; j < 8; j += 4) {
            const int col = tn * 8 + j;
            float4 v;
            v.x = fmaxf(acc[i][j + 0] + bo[col + 0], 0.0f);
            v.y = fmaxf(acc[i][j + 1] + bo[col + 1], 0.0f);
            v.z = fmaxf(acc[i][j + 2] + bo[col + 2], 0.0f);
            v.w = fmaxf(acc[i][j + 3] + bo[col + 3], 0.0f);
            *(float4*)(out + (size_t)row * FOUT + col) = v;
        }
    }
}

// ---------------------------------------------------------------------------
// Launch
// Inputs (metadata order): x, W_s, b_s, W_h, b_h, W_out, b_out, batch(int64)
// ---------------------------------------------------------------------------
extern "C" void kernel_launch(void* const* d_in, const int* in_sizes, int n_in,
                              void* d_out, int out_size)
{
    const float* x   = (const float*)d_in[0];
    const float* Ws  = (const float*)d_in[1];
    const float* bs  = (const float*)d_in[2];
    const float* Wh  = (const float*)d_in[3];
    const float* bh  = (const float*)d_in[4];
    const float* Wo  = (const float*)d_in[5];
    const float* bo  = (const float*)d_in[6];
    // d_in[7] = batch (int64) — graphs are contiguous & equal-size, unused.
    float* out = (float*)d_out;

    k1s_embed<<<NTOT / 64, 256>>>(x, Ws, bs);
    k1h_embed<<<NTOT / 128, 256>>>(x, Wh, bh);
    k2_knn<<<dim3(LG / 128, BG), 128>>>();
    k3_agg<<<NTOT / 16, 256>>>();
    k4_gemm<<<NTOT / 128, 256>>>(x, Wo, bo, out);
}